// round 16
// baseline (speedup 1.0000x reference)
#include <cuda_runtime.h>
#include <cuda_fp16.h>
#include <math.h>
#include <stdint.h>

#define NN   20000
#define EE   320000
#define FIN  386
#define HID  256
#define NOUT 2

#define NKT  13          // 13 * 32 = 416 >= 386 (zero padded)
#define BM   32

// ---------------- scratch (no allocations allowed) ----------------
__device__ int   g_counts[NN];          // zero at module load; k_scan_all re-zeroes
__device__ int   g_rowstart[NN + 1];
__device__ int   g_cursor[NN];
__device__ int   g_csr_src[EE];
__device__ float g_dis[NN];
__device__ __align__(16) uint32_t g_w1bt[(size_t)NKT * 4096];  // W1 fp16, fragment order
__device__ __align__(16) __half g_xw[(size_t)NN * HID];        // x@W1, then scaled by dis
__device__ float g_h2[NN * NOUT];       // dis[n]*(h @ W2)

// ---------------- streams/events for overlap ----------------
static cudaStream_t s_side = nullptr;
static cudaEvent_t  s_evFork = nullptr, s_evScan = nullptr, s_evJoin = nullptr;
namespace {
struct _StreamInit {
    _StreamInit() {
        int lo = 0, hi = 0;
        cudaDeviceGetStreamPriorityRange(&lo, &hi);
        if (cudaStreamCreateWithPriority(&s_side, cudaStreamNonBlocking, hi) != cudaSuccess)
            s_side = nullptr;
        if (cudaEventCreateWithFlags(&s_evFork, cudaEventDisableTiming) != cudaSuccess)
            s_evFork = nullptr;
        if (cudaEventCreateWithFlags(&s_evScan, cudaEventDisableTiming) != cudaSuccess)
            s_evScan = nullptr;
        if (cudaEventCreateWithFlags(&s_evJoin, cudaEventDisableTiming) != cudaSuccess)
            s_evJoin = nullptr;
    }
};
_StreamInit _streamInit;
}

// ---------------- helpers ----------------
__device__ __forceinline__ uint32_t smem_u32(const void* p) {
    uint32_t a;
    asm("{ .reg .u64 t; cvta.to.shared.u64 t, %1; cvt.u32.u64 %0, t; }"
        : "=r"(a) : "l"(p));
    return a;
}
__device__ __forceinline__ void cp_async16(uint32_t saddr, const void* gptr) {
    asm volatile("cp.async.cg.shared.global [%0], [%1], 16;"
                 :: "r"(saddr), "l"(gptr) : "memory");
}
#define CP_COMMIT()  asm volatile("cp.async.commit_group;" ::: "memory")
#define CP_WAIT0()   asm volatile("cp.async.wait_group 0;" ::: "memory")

__device__ __forceinline__ void acc_add_half(float* acc, uint2 v) {
    __half2 h0 = *(__half2*)&v.x;
    __half2 h1 = *(__half2*)&v.y;
    float2 f0 = __half22float2(h0);
    float2 f1 = __half22float2(h1);
    acc[0] += f0.x; acc[1] += f0.y;
    acc[2] += f1.x; acc[3] += f1.y;
}

// ---------------- CSR build ----------------
__global__ void k_count(const int* __restrict__ dst) {
    int e = blockIdx.x * blockDim.x + threadIdx.x;
    if (e < EE) atomicAdd(&g_counts[dst[e]], 1);
}

#define SEG 20
__global__ void __launch_bounds__(1024) k_scan_all() {
    __shared__ int ws[32];
    int t = threadIdx.x, lane = t & 31, wid = t >> 5;
    int start = t * SEG;
    int end = start + SEG; if (end > NN) end = NN;

    int cnt[SEG];
    int m = end - start;
    #pragma unroll
    for (int i = 0; i < SEG; i++)
        cnt[i] = (i < m) ? g_counts[start + i] : 0;

    int sum = 0;
    #pragma unroll
    for (int i = 0; i < SEG; i++) sum += cnt[i];

    int v = sum;
    #pragma unroll
    for (int off = 1; off < 32; off <<= 1) {
        int u = __shfl_up_sync(0xffffffffu, v, off);
        if (lane >= off) v += u;
    }
    if (lane == 31) ws[wid] = v;
    __syncthreads();
    if (wid == 0) {
        int w = ws[lane];
        #pragma unroll
        for (int off = 1; off < 32; off <<= 1) {
            int u = __shfl_up_sync(0xffffffffu, w, off);
            if (lane >= off) w += u;
        }
        ws[lane] = w;
    }
    __syncthreads();
    int incl = v + (wid > 0 ? ws[wid - 1] : 0);
    int run = incl - sum;

    #pragma unroll
    for (int i = 0; i < SEG; i++) {
        if (i < m) {
            int idx = start + i;
            g_counts[idx]   = 0;
            g_rowstart[idx] = run;
            g_cursor[idx]   = run;
            g_dis[idx]      = rsqrtf((float)cnt[i] + 1.0f);
            run += cnt[i];
        }
    }
    if (t == 1023) g_rowstart[NN] = incl;
}

__global__ void k_fill(const int* __restrict__ src, const int* __restrict__ dst) {
    int e = blockIdx.x * blockDim.x + threadIdx.x;
    if (e >= EE) return;
    int d = dst[e];
    int p = atomicAdd(&g_cursor[d], 1);
    g_csr_src[p] = src[e];
}

// ---------------- W1 -> fp16 fragment-order global ----------------
__global__ void k_prepw(const float* __restrict__ W1) {
    int tid = blockIdx.x * blockDim.x + threadIdx.x;
    if (tid >= (NKT * 32 / 2) * HID) return;
    int n  = tid & (HID - 1);
    int kp = tid >> 8;
    int k  = kp * 2;
    float v0 = (k     < FIN) ? W1[(size_t)k       * HID + n] : 0.f;
    float v1 = (k + 1 < FIN) ? W1[(size_t)(k + 1) * HID + n] : 0.f;
    int kt = k >> 5, kc = (k >> 4) & 1, kl = (k >> 3) & 1;
    int lane = (n & 7) * 4 + ((k & 7) >> 1);
    int sub  = (((n >> 3) & 1) << 1) + kl;
    int blk  = ((n >> 4) << 1) + kc;
    __half2 h = __floats2half2_rn(v0, v1);
    g_w1bt[kt * 4096 + (blk * 32 + lane) * 4 + sub] = *(uint32_t*)&h;
}

// ---------------- GEMM1: g_xw = fp16(x @ W1), UNSCALED ----------------
// Round-14 form: CTA 32x256, 128 threads = 4 warps, 1-tile-deep A prefetch.
__global__ void __launch_bounds__(128, 4)
k_gemm1(const float* __restrict__ A) {
    __shared__ __align__(16) uint32_t sA[2][512];    // 2 x 2KB
    __shared__ __align__(16) uint32_t sB[2][4096];   // 2 x 16KB

    const int t    = threadIdx.x;
    const int warp = t >> 5;
    const int lane = t & 31;
    const int wn   = warp;
    const int nbp0 = wn * 4;
    const int qrow = lane >> 2;
    const int qcol = lane & 3;
    const int rowBase = blockIdx.x * BM;

    const uint32_t sB_addr0 = smem_u32(sB[0]);
    const uint32_t sB_addr1 = smem_u32(sB[1]);

    float acc[2][8][4] = {};
    float2 av[4];

    int sAidx[4];
    #pragma unroll
    for (int i = 0; i < 4; i++) {
        int idx = t + i * 128;
        int r = idx >> 4, p = idx & 15;
        int mb = r >> 4, rh = (r >> 3) & 1, qr = r & 7;
        int kc = p >> 3, pp = p & 7, qc = pp & 3, kh = pp >> 2;
        sAidx[i] = (((mb * 2 + kc) * 32) + qr * 4 + qc) * 4 + kh * 2 + rh;
    }

    // ---- prologue
    {
        const uint4* bsrc = (const uint4*)g_w1bt;
        #pragma unroll
        for (int i = 0; i < 8; i++)
            cp_async16(sB_addr0 + (t + i * 128) * 16, bsrc + t + i * 128);
        CP_COMMIT();
        #pragma unroll
        for (int i = 0; i < 4; i++) {
            int idx = t + i * 128;
            int r = idx >> 4, p = idx & 15;
            int gr = rowBase + r, gc = 2 * p;
            av[i] = (gr < NN && gc < FIN) ? *(const float2*)(A + (size_t)gr * FIN + gc)
                                          : make_float2(0.f, 0.f);
        }
        #pragma unroll
        for (int i = 0; i < 4; i++) {
            __half2 h = __floats2half2_rn(av[i].x, av[i].y);
            sA[0][sAidx[i]] = *(uint32_t*)&h;
        }
        CP_WAIT0();
    }
    __syncthreads();

    for (int kt = 0; kt < NKT; kt++) {
        const int cur = kt & 1;
        const int nxt = cur ^ 1;

        if (kt + 1 < NKT) {
            const uint4* bsrc = (const uint4*)(g_w1bt + (size_t)(kt + 1) * 4096);
            uint32_t dstb = (nxt ? sB_addr1 : sB_addr0);
            #pragma unroll
            for (int i = 0; i < 8; i++)
                cp_async16(dstb + (t + i * 128) * 16, bsrc + t + i * 128);
            CP_COMMIT();
            int k0 = (kt + 1) * 32;
            #pragma unroll
            for (int i = 0; i < 4; i++) {
                int idx = t + i * 128;
                int r = idx >> 4, p = idx & 15;
                int gr = rowBase + r, gc = k0 + 2 * p;
                av[i] = (gr < NN && gc < FIN) ? *(const float2*)(A + (size_t)gr * FIN + gc)
                                              : make_float2(0.f, 0.f);
            }
        }

        #pragma unroll
        for (int kc = 0; kc < 2; kc++) {
            uint4 afr[2];
            afr[0] = ((const uint4*)sA[cur])[(kc) * 32 + lane];
            afr[1] = ((const uint4*)sA[cur])[(2 + kc) * 32 + lane];
            #pragma unroll
            for (int j = 0; j < 4; j++) {
                uint4 bf = ((const uint4*)sB[cur])[((nbp0 + j) * 2 + kc) * 32 + lane];
                #pragma unroll
                for (int mi = 0; mi < 2; mi++) {
                    asm volatile(
                        "mma.sync.aligned.m16n8k16.row.col.f32.f16.f16.f32 "
                        "{%0,%1,%2,%3}, {%4,%5,%6,%7}, {%8,%9}, {%0,%1,%2,%3};"
                        : "+f"(acc[mi][2 * j][0]), "+f"(acc[mi][2 * j][1]),
                          "+f"(acc[mi][2 * j][2]), "+f"(acc[mi][2 * j][3])
                        : "r"(afr[mi].x), "r"(afr[mi].y), "r"(afr[mi].z), "r"(afr[mi].w),
                          "r"(bf.x), "r"(bf.y));
                    asm volatile(
                        "mma.sync.aligned.m16n8k16.row.col.f32.f16.f16.f32 "
                        "{%0,%1,%2,%3}, {%4,%5,%6,%7}, {%8,%9}, {%0,%1,%2,%3};"
                        : "+f"(acc[mi][2 * j + 1][0]), "+f"(acc[mi][2 * j + 1][1]),
                          "+f"(acc[mi][2 * j + 1][2]), "+f"(acc[mi][2 * j + 1][3])
                        : "r"(afr[mi].x), "r"(afr[mi].y), "r"(afr[mi].z), "r"(afr[mi].w),
                          "r"(bf.z), "r"(bf.w));
                }
            }
        }

        if (kt + 1 < NKT) {
            #pragma unroll
            for (int i = 0; i < 4; i++) {
                __half2 h = __floats2half2_rn(av[i].x, av[i].y);
                sA[nxt][sAidx[i]] = *(uint32_t*)&h;
            }
            CP_WAIT0();
            __syncthreads();
        }
    }

    // ---- epilogue
    #pragma unroll
    for (int mi = 0; mi < 2; mi++) {
        int r0 = rowBase + mi * 16 + qrow;
        #pragma unroll
        for (int ni = 0; ni < 8; ni++) {
            int col = wn * 64 + ni * 8 + qcol * 2;
            if (r0 < NN)
                *(__half2*)(g_xw + (size_t)r0 * HID + col) =
                    __floats2half2_rn(acc[mi][ni][0], acc[mi][ni][1]);
            if (r0 + 8 < NN)
                *(__half2*)(g_xw + (size_t)(r0 + 8) * HID + col) =
                    __floats2half2_rn(acc[mi][ni][2], acc[mi][ni][3]);
        }
    }
}

// ---------------- scale xw rows by dis ----------------
__global__ void k_scale_xw() {
    int idx = blockIdx.x * blockDim.x + threadIdx.x;   // uint4 index
    if (idx >= NN * 32) return;
    int row = idx >> 5;
    float d = g_dis[row];
    uint4 v = ((uint4*)g_xw)[idx];
    __half2* hp = (__half2*)&v;
    #pragma unroll
    for (int j = 0; j < 4; j++) {
        float2 f = __half22float2(hp[j]);
        hp[j] = __floats2half2_rn(f.x * d, f.y * d);
    }
    ((uint4*)g_xw)[idx] = v;
}

// ---------------- fused agg1 + gemm2: TWO warps per node ----------------
// Each warp handles half a row (uint2 = 4 halfs per lane). 8-deep gather
// batching. Warp pair combines W2 partials through smem.
// Grid divides exactly: NN*2 warps = 40000, 8 warps/block -> 5000 blocks.
__global__ void __launch_bounds__(256) k_agg1_gemm2(
    const float* __restrict__ b1, const float* __restrict__ W2
) {
    __shared__ float sW[HID * NOUT];
    __shared__ float sB[HID];
    __shared__ float sPart[8][2];
    for (int i = threadIdx.x; i < HID * NOUT; i += 256) sW[i] = W2[i];
    for (int i = threadIdx.x; i < HID; i += 256) sB[i] = b1[i];
    __syncthreads();

    int wInB = threadIdx.x >> 5;
    int gw   = blockIdx.x * 8 + wInB;          // 0 .. 2*NN-1 (exact)
    int lane = threadIdx.x & 31;
    int n    = gw >> 1;
    int half = gw & 1;
    float dn = g_dis[n];

    // half-row pointer: row = 64 uint2; this warp's half = 32 uint2
    const uint2* xw = (const uint2*)g_xw;
    const size_t off = (size_t)half * 32 + lane;

    float acc[4] = {}, acc2[4] = {};
    acc_add_half(acc, xw[(size_t)n * 64 + off]);   // self term (pre-scaled)

    int rs = g_rowstart[n];
    int re = g_rowstart[n + 1];
    int p = rs;
    while (p + 8 <= re) {
        int s[8];
        #pragma unroll
        for (int i = 0; i < 8; i++) s[i] = g_csr_src[p + i];
        uint2 v[8];
        #pragma unroll
        for (int i = 0; i < 8; i++) v[i] = xw[(size_t)s[i] * 64 + off];
        #pragma unroll
        for (int i = 0; i < 8; i += 2) {
            acc_add_half(acc,  v[i]);
            acc_add_half(acc2, v[i + 1]);
        }
        p += 8;
    }
    if (p + 4 <= re) {
        int s[4];
        #pragma unroll
        for (int i = 0; i < 4; i++) s[i] = g_csr_src[p + i];
        uint2 v[4];
        #pragma unroll
        for (int i = 0; i < 4; i++) v[i] = xw[(size_t)s[i] * 64 + off];
        acc_add_half(acc,  v[0]);
        acc_add_half(acc2, v[1]);
        acc_add_half(acc,  v[2]);
        acc_add_half(acc2, v[3]);
        p += 4;
    }
    if (p + 2 <= re) {
        uint2 v0 = xw[(size_t)g_csr_src[p]     * 64 + off];
        uint2 v1 = xw[(size_t)g_csr_src[p + 1] * 64 + off];
        acc_add_half(acc,  v0);
        acc_add_half(acc2, v1);
        p += 2;
    }
    if (p < re)
        acc_add_half(acc, xw[(size_t)g_csr_src[p] * 64 + off]);

    // bias + relu + partial W2 contraction over this warp's 128 cols
    int cb = (half * 32 + lane) * 4;
    float s0 = 0.f, s1 = 0.f;
    #pragma unroll
    for (int j = 0; j < 4; j++) {
        float hv = fmaxf(fmaf(dn, acc[j] + acc2[j], sB[cb + j]), 0.f);
        s0 = fmaf(hv, sW[(cb + j) * 2 + 0], s0);
        s1 = fmaf(hv, sW[(cb + j) * 2 + 1], s1);
    }
    #pragma unroll
    for (int o = 16; o > 0; o >>= 1) {
        s0 += __shfl_down_sync(0xffffffffu, s0, o);
        s1 += __shfl_down_sync(0xffffffffu, s1, o);
    }
    if (lane == 0) { sPart[wInB][0] = s0; sPart[wInB][1] = s1; }
    __syncthreads();
    if ((wInB & 1) == 0 && lane == 0) {
        g_h2[n * 2 + 0] = dn * (sPart[wInB][0] + sPart[wInB + 1][0]);
        g_h2[n * 2 + 1] = dn * (sPart[wInB][1] + sPart[wInB + 1][1]);
    }
}

// ---------------- agg2 + tanh (pre-scaled h2; 4-way unroll) ----------------
__global__ void k_agg2(const float* __restrict__ b2, float* __restrict__ out) {
    int n = blockIdx.x * blockDim.x + threadIdx.x;
    if (n >= NN) return;
    float dn = g_dis[n];
    const float2* h2 = (const float2*)g_h2;
    float2 hn = h2[n];
    float a0 = hn.x, a1 = hn.y;
    float b0 = 0.f, b1v = 0.f;
    int rs = g_rowstart[n];
    int re = g_rowstart[n + 1];
    int p = rs;
    for (; p + 4 <= re; p += 4) {
        float2 v0 = h2[g_csr_src[p]];
        float2 v1 = h2[g_csr_src[p + 1]];
        float2 v2 = h2[g_csr_src[p + 2]];
        float2 v3 = h2[g_csr_src[p + 3]];
        a0  += v0.x + v2.x;  a1  += v0.y + v2.y;
        b0  += v1.x + v3.x;  b1v += v1.y + v3.y;
    }
    for (; p < re; p++) {
        float2 v = h2[g_csr_src[p]];
        a0 += v.x; a1 += v.y;
    }
    out[n * 2 + 0] = tanhf(fmaf(dn, a0 + b0,  b2[0]));
    out[n * 2 + 1] = tanhf(fmaf(dn, a1 + b1v, b2[1]));
}

// ---------------- launch ----------------
extern "C" void kernel_launch(void* const* d_in, const int* in_sizes, int n_in,
                              void* d_out, int out_size) {
    const float* x   = (const float*)d_in[0];
    const int*   src = (const int*)  d_in[1];
    const int*   dst = (const int*)  d_in[2];
    const float* W1  = (const float*)d_in[3];
    const float* b1  = (const float*)d_in[4];
    const float* W2  = (const float*)d_in[5];
    const float* b2  = (const float*)d_in[6];
    float* out = (float*)d_out;

    (void)in_sizes; (void)n_in; (void)out_size;

    bool overlap = (s_side && s_evFork && s_evScan && s_evJoin);

    if (overlap) {
        // indices: count0 scan1 prepw2 gemm1(3) scale4 fill5 -> ncu lands on gemm1.
        cudaEventRecord(s_evFork, 0);
        cudaStreamWaitEvent(s_side, s_evFork, 0);

        k_count<<<(EE + 255) / 256, 256, 0, s_side>>>(dst);
        k_scan_all<<<1, 1024, 0, s_side>>>();
        cudaEventRecord(s_evScan, s_side);

        k_prepw<<<((NKT * 16) * HID + 255) / 256, 256>>>(W1);
        k_gemm1<<<(NN + BM - 1) / BM, 128>>>(x);
        cudaStreamWaitEvent(0, s_evScan, 0);     // scale needs g_dis
        k_scale_xw<<<(NN * 32 + 255) / 256, 256>>>();

        k_fill<<<(EE + 255) / 256, 256, 0, s_side>>>(src, dst);
        cudaEventRecord(s_evJoin, s_side);

        cudaStreamWaitEvent(0, s_evJoin, 0);
    } else {
        k_count<<<(EE + 255) / 256, 256>>>(dst);
        k_scan_all<<<1, 1024>>>();
        k_fill<<<(EE + 255) / 256, 256>>>(src, dst);
        k_prepw<<<((NKT * 16) * HID + 255) / 256, 256>>>(W1);
        k_gemm1<<<(NN + BM - 1) / BM, 128>>>(x);
        k_scale_xw<<<(NN * 32 + 255) / 256, 256>>>();
    }

    // two warps per node: 40000 warps, 5000 blocks of 256
    k_agg1_gemm2<<<NN * 2 * 32 / 256, 256>>>(b1, W2);
    k_agg2<<<(NN + 255) / 256, 256>>>(b2, out);
}